// round 10
// baseline (speedup 1.0000x reference)
#include <cuda_runtime.h>
#include <math.h>

#define BB 8
#define NT 512
#define IQ 256
#define DF 768
#define NHEAD 12
#define HD 64
#define PROJ 256
#define HID 128
#define VOC 16384
#define TOPKK 20
#define NSQ (NT*NT)
#define NP (NT+2)

__device__ float g_emb[BB*NT*DF];
__device__ float g_Q[BB*IQ*DF];
__device__ float g_K[BB*NT*DF];
__device__ float g_V[BB*NT*DF];
__device__ float g_S[BB*NHEAD*IQ*NT];
__device__ float g_AO[BB*IQ*DF];
__device__ float g_xp[BB*NP*PROJ];
__device__ float g_h1[BB*NP*HID];
__device__ float g_h2[BB*NP*HID];
__device__ float g_sig[BB*NT];
__device__ float g_sq[BB*NT];
__device__ float g_dsi[BB*NT];
__device__ float g_e[BB*NT*DF];
__device__ float g_Wm[BB*NSQ];
__device__ unsigned char g_mask[BB*NSQ];
__device__ float g_A[BB*NSQ];
__device__ float g_Pinv[BB*64*64];
__device__ float g_Rpan[BB*64*NT];
__device__ float g_Cpan[BB*NT*64];
__device__ float g_w1r[3*HID*PROJ];
__device__ float g_w2r[3*HID*HID];

__global__ void k_emb(const float* __restrict__ ge, const float* __restrict__ ue){
    int idx = blockIdx.x*blockDim.x + threadIdx.x;
    if (idx >= BB*NT*DF) return;
    int f = idx % DF, n = (idx/DF) % NT, b = idx/(DF*NT);
    float v = (n < IQ) ? ge[((size_t)b*IQ+n)*DF+f] : ue[((size_t)b*IQ+(n-IQ))*DF+f];
    float dv = expf(-(float)((f>>1)*2) * (9.210340371976184f/768.0f));
    float ang = (float)n * dv;
    g_emb[idx] = v + ((f&1) ? cosf(ang) : sinf(ang));
}

// ===== 128x128-tile, 8x8-microtile fp32 GEMM, transB only =====
// C[M,N] = scale*A*B^T (+bias) (+C)  OR gram mode (sqv!=0): C=exp(-(max(si+sj-2dot,0))/1536)
// REQUIRES: M%128==0, N%128==0, K%8==0, 16B alignment.
__global__ void __launch_bounds__(256) k_gemm3(
    const float* __restrict__ A, int lda, long long sAb, long long sAh,
    const float* __restrict__ Bm, int ldb, long long sBb, long long sBh,
    float* __restrict__ C, int ldc, long long sCb, long long sCh,
    int K, int hdiv, const float* __restrict__ bias, float scale,
    int accum, const float* __restrict__ sqv)
{
    int z = blockIdx.z, b = z/hdiv, h = z - b*hdiv;
    A  += (size_t)b*sAb + (size_t)h*sAh;
    Bm += (size_t)b*sBb + (size_t)h*sBh;
    C  += (size_t)b*sCb + (size_t)h*sCh;
    __shared__ float As[8][132];
    __shared__ float Bs[8][132];
    int m0 = blockIdx.y*128, n0 = blockIdx.x*128;
    int t = threadIdx.x, tx = t&15, ty = t>>4;
    int lrow = t>>1, lk = (t&1)*4;
    float acc[8][8];
    #pragma unroll
    for (int i=0;i<8;i++)
        #pragma unroll
        for (int j=0;j<8;j++) acc[i][j]=0.f;

    for (int k0=0; k0<K; k0+=8){
        float4 a4 = *(const float4*)&A[(size_t)(m0+lrow)*lda + k0+lk];
        float4 b4 = *(const float4*)&Bm[(size_t)(n0+lrow)*ldb + k0+lk];
        As[lk+0][lrow]=a4.x; As[lk+1][lrow]=a4.y; As[lk+2][lrow]=a4.z; As[lk+3][lrow]=a4.w;
        Bs[lk+0][lrow]=b4.x; Bs[lk+1][lrow]=b4.y; Bs[lk+2][lrow]=b4.z; Bs[lk+3][lrow]=b4.w;
        __syncthreads();
        #pragma unroll
        for (int kk=0;kk<8;kk++){
            float4 a0 = *(float4*)&As[kk][ty*4];
            float4 a1 = *(float4*)&As[kk][64+ty*4];
            float4 b0 = *(float4*)&Bs[kk][tx*4];
            float4 b1 = *(float4*)&Bs[kk][64+tx*4];
            float av[8] = {a0.x,a0.y,a0.z,a0.w,a1.x,a1.y,a1.z,a1.w};
            float bv[8] = {b0.x,b0.y,b0.z,b0.w,b1.x,b1.y,b1.z,b1.w};
            #pragma unroll
            for (int i=0;i<8;i++)
                #pragma unroll
                for (int j=0;j<8;j++) acc[i][j] += av[i]*bv[j];
        }
        __syncthreads();
    }

    if (sqv){
        const float* sb = sqv + (size_t)z*NT;
        float sj[8];
        #pragma unroll
        for (int j=0;j<8;j++) sj[j] = sb[n0 + ((j<4)? tx*4+j : 64+tx*4+j-4)];
        #pragma unroll
        for (int i=0;i<8;i++){
            int r = m0 + ((i<4)? ty*4+i : 64+ty*4+i-4);
            float si = sb[r];
            float v[8];
            #pragma unroll
            for (int j=0;j<8;j++)
                v[j] = expf(-fmaxf(si+sj[j]-2.f*acc[i][j],0.f)*(1.f/1536.f));
            *(float4*)&C[(size_t)r*ldc + n0 + tx*4]      = make_float4(v[0],v[1],v[2],v[3]);
            *(float4*)&C[(size_t)r*ldc + n0 + 64 + tx*4] = make_float4(v[4],v[5],v[6],v[7]);
        }
    } else {
        float bv[8] = {0,0,0,0,0,0,0,0};
        if (bias){
            #pragma unroll
            for (int j=0;j<8;j++) bv[j] = bias[n0 + ((j<4)? tx*4+j : 64+tx*4+j-4)];
        }
        #pragma unroll
        for (int i=0;i<8;i++){
            int r = m0 + ((i<4)? ty*4+i : 64+ty*4+i-4);
            float* c0 = &C[(size_t)r*ldc + n0 + tx*4];
            float* c1 = &C[(size_t)r*ldc + n0 + 64 + tx*4];
            float4 v0 = make_float4(scale*acc[i][0]+bv[0], scale*acc[i][1]+bv[1],
                                    scale*acc[i][2]+bv[2], scale*acc[i][3]+bv[3]);
            float4 v1 = make_float4(scale*acc[i][4]+bv[4], scale*acc[i][5]+bv[5],
                                    scale*acc[i][6]+bv[6], scale*acc[i][7]+bv[7]);
            if (accum){
                float4 o0 = *(float4*)c0, o1 = *(float4*)c1;
                v0.x+=o0.x; v0.y+=o0.y; v0.z+=o0.z; v0.w+=o0.w;
                v1.x+=o1.x; v1.y+=o1.y; v1.z+=o1.z; v1.w+=o1.w;
            }
            *(float4*)c0 = v0;
            *(float4*)c1 = v1;
        }
    }
}

// ===== 128x64-tile 8x4 GEMM (used only for attn@V, N=64) =====
__global__ void __launch_bounds__(256) k_gemm2(
    const float* __restrict__ A, int lda, long long sAb, long long sAh,
    const float* __restrict__ Bm, int ldb, long long sBb, long long sBh,
    float* __restrict__ C, int ldc, long long sCb, long long sCh,
    int K, int hdiv, const float* __restrict__ bias, float scale,
    int accum, int transB)
{
    int z = blockIdx.z, b = z/hdiv, h = z - b*hdiv;
    A  += (size_t)b*sAb + (size_t)h*sAh;
    Bm += (size_t)b*sBb + (size_t)h*sBh;
    C  += (size_t)b*sCb + (size_t)h*sCh;
    __shared__ float As[16][132];
    __shared__ float Bs[16][68];
    int m0 = blockIdx.y*128, n0 = blockIdx.x*64;
    int t = threadIdx.x, tx = t&15, ty = t>>4;
    float acc[8][4];
    #pragma unroll
    for (int i=0;i<8;i++){ acc[i][0]=0;acc[i][1]=0;acc[i][2]=0;acc[i][3]=0; }

    for (int k0=0; k0<K; k0+=16){
        #pragma unroll
        for (int u=0;u<2;u++){
            int li = t + u*256;
            int row = li>>2, kk = (li&3)*4;
            float4 a4 = *(const float4*)&A[(size_t)(m0+row)*lda + k0+kk];
            As[kk+0][row]=a4.x; As[kk+1][row]=a4.y; As[kk+2][row]=a4.z; As[kk+3][row]=a4.w;
        }
        if (transB){
            int n = t>>2, kk = (t&3)*4;
            float4 b4 = *(const float4*)&Bm[(size_t)(n0+n)*ldb + k0+kk];
            Bs[kk+0][n]=b4.x; Bs[kk+1][n]=b4.y; Bs[kk+2][n]=b4.z; Bs[kk+3][n]=b4.w;
        } else {
            int kk = t>>4, n4 = (t&15)*4;
            float4 b4 = *(const float4*)&Bm[(size_t)(k0+kk)*ldb + n0+n4];
            *(float4*)&Bs[kk][n4] = b4;
        }
        __syncthreads();
        #pragma unroll
        for (int kk=0;kk<16;kk++){
            float4 a0 = *(float4*)&As[kk][ty*4];
            float4 a1 = *(float4*)&As[kk][64+ty*4];
            float4 bv = *(float4*)&Bs[kk][tx*4];
            float av[8] = {a0.x,a0.y,a0.z,a0.w,a1.x,a1.y,a1.z,a1.w};
            float bb[4] = {bv.x,bv.y,bv.z,bv.w};
            #pragma unroll
            for (int i=0;i<8;i++)
                #pragma unroll
                for (int j=0;j<4;j++) acc[i][j] += av[i]*bb[j];
        }
        __syncthreads();
    }

    int cb = n0 + tx*4;
    float b0=0,b1=0,b2=0,b3=0;
    if (bias){ b0=bias[cb]; b1=bias[cb+1]; b2=bias[cb+2]; b3=bias[cb+3]; }
    #pragma unroll
    for (int i=0;i<8;i++){
        int r = m0 + ((i<4)? ty*4+i : 64+ty*4+i-4);
        float* cp = &C[(size_t)r*ldc + cb];
        float4 v;
        v.x = scale*acc[i][0]+b0; v.y = scale*acc[i][1]+b1;
        v.z = scale*acc[i][2]+b2; v.w = scale*acc[i][3]+b3;
        if (accum){
            float4 o = *(float4*)cp;
            v.x+=o.x; v.y+=o.y; v.z+=o.z; v.w+=o.w;
        }
        *(float4*)cp = v;
    }
}

__global__ void k_softmax(){
    size_t row = blockIdx.x;
    float* p = g_S + row*NT;
    __shared__ float red[256];
    int t = threadIdx.x;
    float m = fmaxf(p[t], p[t+256]);
    red[t]=m; __syncthreads();
    for (int k=128;k>0;k>>=1){ if (t<k) red[t]=fmaxf(red[t],red[t+k]); __syncthreads(); }
    m = red[0]; __syncthreads();
    float e1 = expf(p[t]-m), e2 = expf(p[t+256]-m);
    p[t]=e1; p[t+256]=e2;
    red[t]=e1+e2; __syncthreads();
    for (int k=128;k>0;k>>=1){ if (t<k) red[t]+=red[t+k]; __syncthreads(); }
    float inv = 1.f/red[0];
    p[t]*=inv; p[t+256]*=inv;
}

__global__ void k_addln(const float* __restrict__ g, const float* __restrict__ be){
    int row = blockIdx.x;                 // B*IQ
    int b = row/IQ, tq = row%IQ;
    float* u = g_emb + ((size_t)(b*NT + IQ + tq))*DF;
    const float* o = g_Q + (size_t)row*DF;
    __shared__ float xs[DF];
    __shared__ float red[256];
    int t = threadIdx.x;
    float s = 0.f;
    for (int f=t;f<DF;f+=256){ float x=u[f]+o[f]; xs[f]=x; s+=x; }
    red[t]=s; __syncthreads();
    for (int k=128;k>0;k>>=1){ if (t<k) red[t]+=red[t+k]; __syncthreads(); }
    float mean = red[0]*(1.f/DF); __syncthreads();
    float v = 0.f;
    for (int f=t;f<DF;f+=256){ float d=xs[f]-mean; v+=d*d; }
    red[t]=v; __syncthreads();
    for (int k=128;k>0;k>>=1){ if (t<k) red[t]+=red[t+k]; __syncthreads(); }
    float rstd = rsqrtf(red[0]*(1.f/DF) + 1e-5f);
    for (int f=t;f<DF;f+=256) u[f] = (xs[f]-mean)*rstd*g[f] + be[f];
}

__global__ void k_repack(const float* __restrict__ c1w, const float* __restrict__ c2w){
    int idx = blockIdx.x*blockDim.x + threadIdx.x;
    const int t1 = 3*HID*PROJ;
    if (idx < t1){
        int dt = idx/(HID*PROJ), r = idx%(HID*PROJ);
        g_w1r[idx] = c1w[r*3 + dt];
    } else if (idx < t1 + 3*HID*HID){
        int k = idx - t1;
        int dt = k/(HID*HID), r = k%(HID*HID);
        g_w2r[k] = c2w[r*3 + dt];
    }
}

__global__ void k_zeropad(){
    int idx = blockIdx.x*blockDim.x + threadIdx.x;
    if (idx < BB*PROJ){
        int b = idx/PROJ, c = idx%PROJ;
        g_xp[((size_t)b*NP)*PROJ + c] = 0.f;
        g_xp[((size_t)b*NP + NT+1)*PROJ + c] = 0.f;
    }
    if (idx < BB*HID){
        int b = idx/HID, c = idx%HID;
        g_h1[((size_t)b*NP)*HID + c] = 0.f;
        g_h1[((size_t)b*NP + NT+1)*HID + c] = 0.f;
    }
}

__global__ void k_bnrelu(float* buf, const float* __restrict__ g, const float* __restrict__ b, int C){
    int idx = blockIdx.x*blockDim.x + threadIdx.x;
    if (idx >= BB*NT*C) return;
    int c = idx % C, n = (idx/C) % NT, bb = idx/(C*NT);
    size_t off = ((size_t)bb*NP + n + 1)*C + c;
    float x = buf[off]*0.9999950000374997f;   // 1/sqrt(1+1e-5)
    x = x*g[c] + b[c];
    buf[off] = x > 0.f ? x : 0.f;
}

__global__ void k_sigma(const float* __restrict__ ow, const float* __restrict__ ob){
    int row = blockIdx.x;                 // B*NT
    int b = row/NT, n = row%NT;
    int t = threadIdx.x;                  // 128
    __shared__ float red[128];
    red[t] = g_h2[((size_t)b*NP + n + 1)*HID + t] * ow[t];
    __syncthreads();
    for (int k=64;k>0;k>>=1){ if (t<k) red[t]+=red[t+k]; __syncthreads(); }
    if (t == 0) g_sig[row] = red[0] + ob[0];
}

// e = emb/(sigma+eps) and sq[row] = ||e_row||^2
__global__ void k_e(){
    int row = blockIdx.x;                 // B*NT
    int t = threadIdx.x;                  // 256
    float inv = 1.f/(g_sig[row] + 1e-6f);
    const float* src = g_emb + (size_t)row*DF;
    float* dst = g_e + (size_t)row*DF;
    float s = 0.f;
    for (int f=t;f<DF;f+=256){
        float v = src[f]*inv;
        dst[f] = v;
        s += v*v;
    }
    for (int off=16;off;off>>=1) s += __shfl_down_sync(0xFFFFFFFFu, s, off);
    __shared__ float ws[8];
    if ((t&31)==0) ws[t>>5] = s;
    __syncthreads();
    if (t == 0){
        float tot = ws[0];
        #pragma unroll
        for (int w=1;w<8;w++) tot += ws[w];
        g_sq[row] = tot;
    }
}

__global__ void k_topk(){
    int row = blockIdx.x;                 // B*NT
    const float* wr = g_Wm + (size_t)row*NT;
    unsigned char* mr = g_mask + (size_t)row*NT;
    __shared__ float vals[NT];
    __shared__ float wmax[8];
    __shared__ int   wimax[8];
    int t = threadIdx.x, lane = t&31, warp = t>>5;
    vals[t]=wr[t]; vals[t+256]=wr[t+256]; mr[t]=0; mr[t+256]=0;
    __syncthreads();
    for (int it=0; it<TOPKK; it++){
        float v1 = vals[t], v2 = vals[t+256];
        float bv; int bi;
        if (v1 >= v2){ bv=v1; bi=t; } else { bv=v2; bi=t+256; }
        #pragma unroll
        for (int off=16;off;off>>=1){
            float ov = __shfl_down_sync(0xFFFFFFFFu, bv, off);
            int   oi = __shfl_down_sync(0xFFFFFFFFu, bi, off);
            if (ov > bv || (ov==bv && oi<bi)){ bv=ov; bi=oi; }
        }
        if (lane==0){ wmax[warp]=bv; wimax[warp]=bi; }
        __syncthreads();
        if (t == 0){
            bv = wmax[0]; bi = wimax[0];
            #pragma unroll
            for (int w=1;w<8;w++)
                if (wmax[w] > bv || (wmax[w]==bv && wimax[w]<bi)){ bv=wmax[w]; bi=wimax[w]; }
            mr[bi] = 1; vals[bi] = -2e30f;
        }
        __syncthreads();
    }
}

__global__ void k_wmdeg(){
    int row = blockIdx.x;                 // B*NT
    int b = row/NT, i = row%NT;
    float* wr = g_Wm + (size_t)row*NT;
    const unsigned char* mr = g_mask + (size_t)row*NT;
    __shared__ float red[256];
    int t = threadIdx.x;
    float s = 0.f;
    for (int j=t;j<NT;j+=256){
        int m = mr[j] | g_mask[((size_t)b*NT + j)*NT + i];
        float w = m ? wr[j] : 0.f;
        wr[j] = w; s += w;
    }
    red[t]=s; __syncthreads();
    for (int k=128;k>0;k>>=1){ if (t<k) red[t]+=red[t+k]; __syncthreads(); }
    if (t == 0) g_dsi[row] = sqrtf(1.0f/(red[0] + 1e-6f));
}

__global__ void k_buildA(const float* __restrict__ alpha){
    int idx = blockIdx.x*blockDim.x + threadIdx.x;
    if (idx >= BB*NSQ) return;
    int b = idx/NSQ, rem = idx - b*NSQ;
    int i = rem/NT, j = rem%NT;
    float v = -alpha[0] * g_dsi[b*NT+i] * g_Wm[idx] * g_dsi[b*NT+j];
    if (i == j) v += 1.0f + 1e-6f;
    g_A[idx] = v;
}

// merged: blocks [0,BB) invert pivot block; blocks [BB,..) copy row/col panels
__global__ void k_step1(int s){
    if (blockIdx.x < BB){
        int b = blockIdx.x;
        __shared__ float P[64][65];
        __shared__ float rb[64], cb[64];
        __shared__ float pvs;
        int t = threadIdx.x;
        float* Ab = g_A + (size_t)b*NSQ;
        for (int e=t;e<4096;e+=256)
            P[e>>6][e&63] = Ab[(size_t)(s*64 + (e>>6))*NT + s*64 + (e&63)];
        __syncthreads();
        for (int k=0;k<64;k++){
            if (t < 64){ rb[t] = P[k][t]; cb[t] = P[t][k]; }
            __syncthreads();
            if (t == 0) pvs = 1.0f/rb[k];
            __syncthreads();
            float pv = pvs;
            for (int e=t;e<4096;e+=256){
                int i = e>>6, j = e&63;
                float nv;
                if (i == k)      nv = (j == k) ? pv : rb[j]*pv;
                else if (j == k) nv = -cb[i]*pv;
                else             nv = P[i][j] - cb[i]*rb[j]*pv;
                P[i][j] = nv;
            }
            __syncthreads();
        }
        for (int e=t;e<4096;e+=256)
            g_Pinv[(size_t)b*4096 + e] = P[e>>6][e&63];
    } else {
        int idx = (blockIdx.x - BB)*256 + threadIdx.x;
        const int per = 2*64*NT;
        if (idx >= BB*per) return;
        int b = idx/per, r2 = idx - b*per;
        if (r2 < 64*NT){
            int r = r2/NT, j = r2%NT;
            g_Rpan[(size_t)b*64*NT + r2] = g_A[(size_t)b*NSQ + (size_t)(s*64+r)*NT + j];
        } else {
            int r3 = r2 - 64*NT;
            g_Cpan[(size_t)b*NT*64 + r3] = g_A[(size_t)b*NSQ + (size_t)(r3>>6)*NT + s*64 + (r3&63)];
        }
    }
}

__global__ void k_updpan(int s){
    int b = blockIdx.z;
    int job = blockIdx.x;                 // 0..7 row tiles, 8..15 col tiles
    __shared__ float Pv[64][65];
    __shared__ float T[64][65];
    int t = threadIdx.x, tx = t&15, ty = t>>4;
    float* Ab = g_A + (size_t)b*NSQ;
    for (int e=t;e<4096;e+=256) Pv[e>>6][e&63] = g_Pinv[(size_t)b*4096 + e];
    if (job < 8){
        int jb = job;
        if (jb == s){
            __syncthreads();
            for (int e=t;e<4096;e+=256)
                Ab[(size_t)(s*64 + (e>>6))*NT + s*64 + (e&63)] = Pv[e>>6][e&63];
            return;
        }
        for (int e=t;e<4096;e+=256)
            T[e>>6][e&63] = g_Rpan[(size_t)b*64*NT + (size_t)(e>>6)*NT + jb*64 + (e&63)];
        __syncthreads();
        float acc[4][4];
        #pragma unroll
        for (int i=0;i<4;i++){ acc[i][0]=0;acc[i][1]=0;acc[i][2]=0;acc[i][3]=0; }
        for (int kk=0;kk<64;kk++){
            float a[4], bb[4];
            #pragma unroll
            for (int i=0;i<4;i++){ a[i]=Pv[ty+16*i][kk]; bb[i]=T[kk][tx+16*i]; }
            #pragma unroll
            for (int i=0;i<4;i++)
                #pragma unroll
                for (int j=0;j<4;j++) acc[i][j] += a[i]*bb[j];
        }
        #pragma unroll
        for (int i=0;i<4;i++)
            #pragma unroll
            for (int j=0;j<4;j++)
                Ab[(size_t)(s*64 + ty+16*i)*NT + jb*64 + tx+16*j] = acc[i][j];
    } else {
        int ib = job - 8;
        if (ib == s) return;
        for (int e=t;e<4096;e+=256)
            T[e>>6][e&63] = g_Cpan[((size_t)b*NT + ib*64 + (e>>6))*64 + (e&63)];
        __syncthreads();
        float acc[4][4];
        #pragma unroll
        for (int i=0;i<4;i++){ acc[i][0]=0;acc[i][1]=0;acc[i][2]=0;acc[i][3]=0; }
        for (int kk=0;kk<64;kk++){
            float a[4], bb[4];
            #pragma unroll
            for (int i=0;i<4;i++){ a[i]=T[ty+16*i][kk]; bb[i]=Pv[kk][tx+16*i]; }
            #pragma unroll
            for (int i=0;i<4;i++)
                #pragma unroll
                for (int j=0;j<4;j++) acc[i][j] += a[i]*bb[j];
        }
        #pragma unroll
        for (int i=0;i<4;i++)
            #pragma unroll
            for (int j=0;j<4;j++)
                Ab[(size_t)(ib*64 + ty+16*i)*NT + s*64 + tx+16*j] = -acc[i][j];
    }
}

__global__ void k_interior(int s){
    int b = blockIdx.z, bi = blockIdx.y, bj = blockIdx.x;
    if (bi == s || bj == s) return;
    __shared__ float Ct[64][65];
    __shared__ float Rt[64][65];
    int t = threadIdx.x, tx = t&15, ty = t>>4;
    float* Ab = g_A + (size_t)b*NSQ;
    for (int e=t;e<4096;e+=256){
        int r = e>>6, c = e&63;
        Ct[r][c] = g_Cpan[((size_t)b*NT + bi*64 + r)*64 + c];
        Rt[r][c] = Ab[(size_t)(s*64 + r)*NT + bj*64 + c];   // NEW row panel
    }
    __syncthreads();
    float acc[4][4];
    #pragma unroll
    for (int i=0;i<4;i++){ acc[i][0]=0;acc[i][1]=0;acc[i][2]=0;acc[i][3]=0; }
    for (int kk=0;kk<64;kk++){
        float a[4], bb[4];
        #pragma unroll
        for (int i=0;i<4;i++){ a[i]=Ct[ty+16*i][kk]; bb[i]=Rt[kk][tx+16*i]; }
        #pragma unroll
        for (int i=0;i<4;i++)
            #pragma unroll
            for (int j=0;j<4;j++) acc[i][j] += a[i]*bb[j];
    }
    #pragma unroll
    for (int i=0;i<4;i++)
        #pragma unroll
        for (int j=0;j<4;j++)
            Ab[(size_t)(bi*64 + ty+16*i)*NT + bj*64 + tx+16*j] -= acc[i][j];
}

// per-row vocab accumulation in smem (64KB dynamic), then streamed out. No global memset.
__global__ void k_scatter(const int* __restrict__ labels, float* __restrict__ out){
    extern __shared__ float acc[];        // VOC floats
    int row = blockIdx.x;                 // B*NT
    int b = row/NT;
    int t = threadIdx.x;
    float4 z4 = {0.f,0.f,0.f,0.f};
    #pragma unroll
    for (int u=0;u<16;u++) *(float4*)&acc[(t + u*256)*4] = z4;
    __syncthreads();
    const float* pr = g_A + (size_t)row*NT;
    for (int m=t; m<NT; m+=256){
        int v = labels[b*NT + m];
        if ((unsigned)v < (unsigned)VOC) atomicAdd(&acc[v], pr[m]);
    }
    __syncthreads();
    float* orow = out + (size_t)row*VOC;
    #pragma unroll
    for (int u=0;u<16;u++){
        int i4 = (t + u*256)*4;
        *(float4*)&orow[i4] = *(float4*)&acc[i4];
    }
}

extern "C" void kernel_launch(void* const* d_in, const int* in_sizes, int n_in,
                              void* d_out, int out_size)
{
    const float* ge        = (const float*)d_in[0];
    const float* ue        = (const float*)d_in[1];
    const float* hs        = (const float*)d_in[2];
    const int*   labels    = (const int*)  d_in[3];
    const float* mha_in_w  = (const float*)d_in[4];
    const float* mha_in_b  = (const float*)d_in[5];
    const float* mha_out_w = (const float*)d_in[6];
    const float* mha_out_b = (const float*)d_in[7];
    const float* ln_g      = (const float*)d_in[8];
    const float* ln_b      = (const float*)d_in[9];
    const float* proj_w    = (const float*)d_in[10];
    const float* proj_b    = (const float*)d_in[11];
    const float* c1w       = (const float*)d_in[12];
    const float* c1b       = (const float*)d_in[13];
    const float* bn1g      = (const float*)d_in[14];
    const float* bn1b      = (const float*)d_in[15];
    const float* c2w       = (const float*)d_in[16];
    const float* c2b       = (const float*)d_in[17];
    const float* bn2g      = (const float*)d_in[18];
    const float* bn2b      = (const float*)d_in[19];
    const float* ow        = (const float*)d_in[20];
    const float* ob        = (const float*)d_in[21];
    const float* alpha     = (const float*)d_in[22];
    float* out = (float*)d_out;

    float *emb,*Q,*K,*V,*S,*AO,*xp,*h1,*h2,*e,*Wm,*sq,*w1r,*w2r;
    cudaGetSymbolAddress((void**)&emb, g_emb);
    cudaGetSymbolAddress((void**)&Q,   g_Q);
    cudaGetSymbolAddress((void**)&K,   g_K);
    cudaGetSymbolAddress((void**)&V,   g_V);
    cudaGetSymbolAddress((void**)&S,   g_S);
    cudaGetSymbolAddress((void**)&AO,  g_AO);
    cudaGetSymbolAddress((void**)&xp,  g_xp);
    cudaGetSymbolAddress((void**)&h1,  g_h1);
    cudaGetSymbolAddress((void**)&h2,  g_h2);
    cudaGetSymbolAddress((void**)&e,   g_e);
    cudaGetSymbolAddress((void**)&Wm,  g_Wm);
    cudaGetSymbolAddress((void**)&sq,  g_sq);
    cudaGetSymbolAddress((void**)&w1r, g_w1r);
    cudaGetSymbolAddress((void**)&w2r, g_w2r);

    cudaFuncSetAttribute(k_scatter, cudaFuncAttributeMaxDynamicSharedMemorySize, VOC*4);

    dim3 thr(256);

    k_emb<<<(BB*NT*DF+255)/256,256>>>(ge, ue);

    // QKV projections
    k_gemm3<<<dim3(6,2,BB), thr>>>(emb + (size_t)IQ*DF, DF, (long long)NT*DF, 0,
        mha_in_w, DF, 0, 0, Q, DF, (long long)IQ*DF, 0, DF, 1, mha_in_b, 1.f, 0, nullptr);
    k_gemm3<<<dim3(6,4,BB), thr>>>(hs, DF, (long long)NT*DF, 0,
        mha_in_w + DF*DF, DF, 0, 0, K, DF, (long long)NT*DF, 0, DF, 1, mha_in_b+DF, 1.f, 0, nullptr);
    k_gemm3<<<dim3(6,4,BB), thr>>>(hs, DF, (long long)NT*DF, 0,
        mha_in_w + 2*DF*DF, DF, 0, 0, V, DF, (long long)NT*DF, 0, DF, 1, mha_in_b+2*DF, 1.f, 0, nullptr);

    // attention
    k_gemm3<<<dim3(4,2,BB*NHEAD), thr>>>(Q, DF, (long long)IQ*DF, HD,
        K, DF, (long long)NT*DF, HD, S, NT, (long long)NHEAD*IQ*NT, (long long)IQ*NT,
        HD, NHEAD, nullptr, 0.125f, 0, nullptr);
    k_softmax<<<BB*NHEAD*IQ, 256>>>();
    k_gemm2<<<dim3(1,2,BB*NHEAD), thr>>>(S, NT, (long long)NHEAD*IQ*NT, (long long)IQ*NT,
        V, DF, (long long)NT*DF, HD, AO, DF, (long long)IQ*DF, HD,
        NT, NHEAD, nullptr, 1.f, 0, 0);

    // out proj -> g_Q, residual + LN
    k_gemm3<<<dim3(6,2,BB), thr>>>(AO, DF, (long long)IQ*DF, 0,
        mha_out_w, DF, 0, 0, Q, DF, (long long)IQ*DF, 0, DF, 1, mha_out_b, 1.f, 0, nullptr);
    k_addln<<<BB*IQ, 256>>>(ln_g, ln_b);

    // proj + conv stack
    k_repack<<<(3*HID*PROJ + 3*HID*HID + 255)/256,256>>>(c1w, c2w);
    k_zeropad<<<(BB*PROJ+255)/256,256>>>();
    k_gemm3<<<dim3(2,4,BB), thr>>>(emb, DF, (long long)NT*DF, 0,
        proj_w, DF, 0, 0, xp + PROJ, PROJ, (long long)NP*PROJ, 0,
        DF, 1, proj_b, 1.f, 0, nullptr);
    for (int dt=0; dt<3; dt++)
        k_gemm3<<<dim3(1,4,BB), thr>>>(xp + dt*PROJ, PROJ, (long long)NP*PROJ, 0,
            w1r + dt*HID*PROJ, PROJ, 0, 0, h1 + HID, HID, (long long)NP*HID, 0,
            PROJ, 1, dt==0?c1b:nullptr, 1.f, dt>0, nullptr);
    k_bnrelu<<<(BB*NT*HID+255)/256,256>>>(h1, bn1g, bn1b, HID);
    for (int dt=0; dt<3; dt++)
        k_gemm3<<<dim3(1,4,BB), thr>>>(h1 + dt*HID, HID, (long long)NP*HID, 0,
            w2r + dt*HID*HID, HID, 0, 0, h2 + HID, HID, (long long)NP*HID, 0,
            HID, 1, dt==0?c2b:nullptr, 1.f, dt>0, nullptr);
    k_bnrelu<<<(BB*NT*HID+255)/256,256>>>(h2, bn2g, bn2b, HID);
    k_sigma<<<BB*NT, HID>>>(ow, ob);

    // e + row norms, fused gram->W, topk mask, degrees, A
    k_e<<<BB*NT, 256>>>();
    k_gemm3<<<dim3(4,4,BB), thr>>>(e, DF, (long long)NT*DF, 0,
        e, DF, (long long)NT*DF, 0, Wm, NT, (long long)NSQ, 0,
        DF, 1, nullptr, 1.f, 0, sq);
    k_topk<<<BB*NT, 256>>>();
    k_wmdeg<<<BB*NT, 256>>>();
    k_buildA<<<(BB*NSQ+255)/256,256>>>(alpha);

    // blocked Gauss-Jordan inversion (SPD, no pivoting), nb=64
    for (int s=0; s<8; s++){
        k_step1<<<BB + (BB*2*64*NT+255)/256, 256>>>(s);
        k_updpan<<<dim3(16,1,BB), 256>>>(s);
        k_interior<<<dim3(8,8,BB), 256>>>(s);
    }

    // out = prop @ one_hot(labels): smem-resident per-row scatter
    k_scatter<<<BB*NT, 256, VOC*4>>>(labels, out);
}

// round 11
// speedup vs baseline: 1.1644x; 1.1644x over previous
#include <cuda_runtime.h>
#include <math.h>

#define BB 8
#define NT 512
#define IQ 256
#define DF 768
#define NHEAD 12
#define HD 64
#define PROJ 256
#define HID 128
#define VOC 16384
#define TOPKK 20
#define NSQ (NT*NT)
#define NP (NT+2)

__device__ float g_emb[BB*NT*DF];
__device__ float g_Q[BB*IQ*DF];
__device__ float g_K[BB*NT*DF];
__device__ float g_V[BB*NT*DF];
__device__ float g_S[BB*NHEAD*IQ*NT];
__device__ float g_AO[BB*IQ*DF];
__device__ float g_xp[BB*NP*PROJ];
__device__ float g_h1[BB*NP*HID];
__device__ float g_h2[BB*NP*HID];
__device__ float g_sig[BB*NT];
__device__ float g_sq[BB*NT];
__device__ float g_dsi[BB*NT];
__device__ float g_e[BB*NT*DF];
__device__ float g_Wm[BB*NSQ];
__device__ unsigned char g_mask[BB*NSQ];
__device__ unsigned char g_mask2[BB*NSQ];
__device__ float g_A[BB*NSQ];
__device__ float g_Pinv[BB*64*64];
__device__ float g_Rpan[BB*64*NT];
__device__ float g_Cpan[BB*NT*64];
__device__ float g_w1r[3*HID*PROJ];
__device__ float g_w2r[3*HID*HID];

__global__ void k_emb(const float* __restrict__ ge, const float* __restrict__ ue){
    int idx = blockIdx.x*blockDim.x + threadIdx.x;
    if (idx >= BB*NT*DF) return;
    int f = idx % DF, n = (idx/DF) % NT, b = idx/(DF*NT);
    float v = (n < IQ) ? ge[((size_t)b*IQ+n)*DF+f] : ue[((size_t)b*IQ+(n-IQ))*DF+f];
    float dv = expf(-(float)((f>>1)*2) * (9.210340371976184f/768.0f));
    float ang = (float)n * dv;
    g_emb[idx] = v + ((f&1) ? cosf(ang) : sinf(ang));
}

// ===== 128x64-tile, 8x4-microtile fp32 GEMM, double-buffered smem =====
// C = scale*A*op(B) (+bias) (+C)  OR gram mode (sqv!=0): C=exp(-(max(si+sj-2dot,0))/1536)
// REQUIRES: M%128==0, N%64==0, K%16==0, 16B alignment.
__global__ void __launch_bounds__(256) k_gemm2(
    const float* __restrict__ A, int lda, long long sAb, long long sAh,
    const float* __restrict__ Bm, int ldb, long long sBb, long long sBh,
    float* __restrict__ C, int ldc, long long sCb, long long sCh,
    int K, int hdiv, const float* __restrict__ bias, float scale,
    int accum, int transB, const float* __restrict__ sqv)
{
    int z = blockIdx.z, b = z/hdiv, h = z - b*hdiv;
    A  += (size_t)b*sAb + (size_t)h*sAh;
    Bm += (size_t)b*sBb + (size_t)h*sBh;
    C  += (size_t)b*sCb + (size_t)h*sCh;
    __shared__ float As[2][16][132];
    __shared__ float Bs[2][16][68];
    int m0 = blockIdx.y*128, n0 = blockIdx.x*64;
    int t = threadIdx.x, tx = t&15, ty = t>>4;
    int ar = t>>2, ak = (t&3)*4;          // A loader: rows ar, ar+64; k-offset ak
    int bn = t>>2;                        // B transB loader: n row
    int bk = t>>4, bn4 = (t&15)*4;        // B notrans loader
    float acc[8][4];
    #pragma unroll
    for (int i=0;i<8;i++){ acc[i][0]=0;acc[i][1]=0;acc[i][2]=0;acc[i][3]=0; }

    // prologue: tile 0 -> buffer 0
    {
        float4 a0 = *(const float4*)&A[(size_t)(m0+ar)*lda + ak];
        float4 a1 = *(const float4*)&A[(size_t)(m0+ar+64)*lda + ak];
        As[0][ak+0][ar]=a0.x; As[0][ak+1][ar]=a0.y; As[0][ak+2][ar]=a0.z; As[0][ak+3][ar]=a0.w;
        As[0][ak+0][ar+64]=a1.x; As[0][ak+1][ar+64]=a1.y; As[0][ak+2][ar+64]=a1.z; As[0][ak+3][ar+64]=a1.w;
        if (transB){
            float4 b4 = *(const float4*)&Bm[(size_t)(n0+bn)*ldb + ak];
            Bs[0][ak+0][bn]=b4.x; Bs[0][ak+1][bn]=b4.y; Bs[0][ak+2][bn]=b4.z; Bs[0][ak+3][bn]=b4.w;
        } else {
            float4 b4 = *(const float4*)&Bm[(size_t)bk*ldb + n0+bn4];
            *(float4*)&Bs[0][bk][bn4] = b4;
        }
    }
    __syncthreads();

    int ntile = K>>4, buf = 0;
    for (int it=0; it<ntile; it++){
        float4 na0, na1, nb;
        bool pf = (it+1 < ntile);
        if (pf){
            int k0 = (it+1)<<4;
            na0 = *(const float4*)&A[(size_t)(m0+ar)*lda + k0+ak];
            na1 = *(const float4*)&A[(size_t)(m0+ar+64)*lda + k0+ak];
            nb  = transB ? *(const float4*)&Bm[(size_t)(n0+bn)*ldb + k0+ak]
                         : *(const float4*)&Bm[(size_t)(k0+bk)*ldb + n0+bn4];
        }
        #pragma unroll
        for (int kk=0;kk<16;kk++){
            float4 a0 = *(float4*)&As[buf][kk][ty*4];
            float4 a1 = *(float4*)&As[buf][kk][64+ty*4];
            float4 bv = *(float4*)&Bs[buf][kk][tx*4];
            float av[8] = {a0.x,a0.y,a0.z,a0.w,a1.x,a1.y,a1.z,a1.w};
            float bb[4] = {bv.x,bv.y,bv.z,bv.w};
            #pragma unroll
            for (int i=0;i<8;i++)
                #pragma unroll
                for (int j=0;j<4;j++) acc[i][j] += av[i]*bb[j];
        }
        if (pf){
            int nbuf = buf^1;
            As[nbuf][ak+0][ar]=na0.x; As[nbuf][ak+1][ar]=na0.y; As[nbuf][ak+2][ar]=na0.z; As[nbuf][ak+3][ar]=na0.w;
            As[nbuf][ak+0][ar+64]=na1.x; As[nbuf][ak+1][ar+64]=na1.y; As[nbuf][ak+2][ar+64]=na1.z; As[nbuf][ak+3][ar+64]=na1.w;
            if (transB){
                Bs[nbuf][ak+0][bn]=nb.x; Bs[nbuf][ak+1][bn]=nb.y; Bs[nbuf][ak+2][bn]=nb.z; Bs[nbuf][ak+3][bn]=nb.w;
            } else {
                *(float4*)&Bs[nbuf][bk][bn4] = nb;
            }
            __syncthreads();
            buf = nbuf;
        }
    }

    int cb = n0 + tx*4;
    if (sqv){
        const float* sb = sqv + (size_t)z*NT;
        float sj0=sb[cb], sj1=sb[cb+1], sj2=sb[cb+2], sj3=sb[cb+3];
        #pragma unroll
        for (int i=0;i<8;i++){
            int r = m0 + ((i<4)? ty*4+i : 64+ty*4+i-4);
            float si = sb[r];
            float4 v;
            v.x = expf(-fmaxf(si+sj0-2.f*acc[i][0],0.f)*(1.f/1536.f));
            v.y = expf(-fmaxf(si+sj1-2.f*acc[i][1],0.f)*(1.f/1536.f));
            v.z = expf(-fmaxf(si+sj2-2.f*acc[i][2],0.f)*(1.f/1536.f));
            v.w = expf(-fmaxf(si+sj3-2.f*acc[i][3],0.f)*(1.f/1536.f));
            *(float4*)&C[(size_t)r*ldc + cb] = v;
        }
    } else {
        float b0=0,b1=0,b2=0,b3=0;
        if (bias){ b0=bias[cb]; b1=bias[cb+1]; b2=bias[cb+2]; b3=bias[cb+3]; }
        #pragma unroll
        for (int i=0;i<8;i++){
            int r = m0 + ((i<4)? ty*4+i : 64+ty*4+i-4);
            float* cp = &C[(size_t)r*ldc + cb];
            float4 v;
            v.x = scale*acc[i][0]+b0; v.y = scale*acc[i][1]+b1;
            v.z = scale*acc[i][2]+b2; v.w = scale*acc[i][3]+b3;
            if (accum){
                float4 o = *(float4*)cp;
                v.x+=o.x; v.y+=o.y; v.z+=o.z; v.w+=o.w;
            }
            *(float4*)cp = v;
        }
    }
}

__global__ void k_softmax(){
    size_t row = blockIdx.x;
    float* p = g_S + row*NT;
    __shared__ float red[256];
    int t = threadIdx.x;
    float m = fmaxf(p[t], p[t+256]);
    red[t]=m; __syncthreads();
    for (int k=128;k>0;k>>=1){ if (t<k) red[t]=fmaxf(red[t],red[t+k]); __syncthreads(); }
    m = red[0]; __syncthreads();
    float e1 = expf(p[t]-m), e2 = expf(p[t+256]-m);
    p[t]=e1; p[t+256]=e2;
    red[t]=e1+e2; __syncthreads();
    for (int k=128;k>0;k>>=1){ if (t<k) red[t]+=red[t+k]; __syncthreads(); }
    float inv = 1.f/red[0];
    p[t]*=inv; p[t+256]*=inv;
}

__global__ void k_addln(const float* __restrict__ g, const float* __restrict__ be){
    int row = blockIdx.x;                 // B*IQ
    int b = row/IQ, tq = row%IQ;
    float* u = g_emb + ((size_t)(b*NT + IQ + tq))*DF;
    const float* o = g_Q + (size_t)row*DF;
    __shared__ float xs[DF];
    __shared__ float red[256];
    int t = threadIdx.x;
    float s = 0.f;
    for (int f=t;f<DF;f+=256){ float x=u[f]+o[f]; xs[f]=x; s+=x; }
    red[t]=s; __syncthreads();
    for (int k=128;k>0;k>>=1){ if (t<k) red[t]+=red[t+k]; __syncthreads(); }
    float mean = red[0]*(1.f/DF); __syncthreads();
    float v = 0.f;
    for (int f=t;f<DF;f+=256){ float d=xs[f]-mean; v+=d*d; }
    red[t]=v; __syncthreads();
    for (int k=128;k>0;k>>=1){ if (t<k) red[t]+=red[t+k]; __syncthreads(); }
    float rstd = rsqrtf(red[0]*(1.f/DF) + 1e-5f);
    for (int f=t;f<DF;f+=256) u[f] = (xs[f]-mean)*rstd*g[f] + be[f];
}

__global__ void k_repack(const float* __restrict__ c1w, const float* __restrict__ c2w){
    int idx = blockIdx.x*blockDim.x + threadIdx.x;
    const int t1 = 3*HID*PROJ;
    if (idx < t1){
        int dt = idx/(HID*PROJ), r = idx%(HID*PROJ);
        g_w1r[idx] = c1w[r*3 + dt];
    } else if (idx < t1 + 3*HID*HID){
        int k = idx - t1;
        int dt = k/(HID*HID), r = k%(HID*HID);
        g_w2r[k] = c2w[r*3 + dt];
    }
}

__global__ void k_zeropad(){
    int idx = blockIdx.x*blockDim.x + threadIdx.x;
    if (idx < BB*PROJ){
        int b = idx/PROJ, c = idx%PROJ;
        g_xp[((size_t)b*NP)*PROJ + c] = 0.f;
        g_xp[((size_t)b*NP + NT+1)*PROJ + c] = 0.f;
    }
    if (idx < BB*HID){
        int b = idx/HID, c = idx%HID;
        g_h1[((size_t)b*NP)*HID + c] = 0.f;
        g_h1[((size_t)b*NP + NT+1)*HID + c] = 0.f;
    }
}

__global__ void k_bnrelu(float* buf, const float* __restrict__ g, const float* __restrict__ b, int C){
    int idx = blockIdx.x*blockDim.x + threadIdx.x;
    if (idx >= BB*NT*C) return;
    int c = idx % C, n = (idx/C) % NT, bb = idx/(C*NT);
    size_t off = ((size_t)bb*NP + n + 1)*C + c;
    float x = buf[off]*0.9999950000374997f;   // 1/sqrt(1+1e-5)
    x = x*g[c] + b[c];
    buf[off] = x > 0.f ? x : 0.f;
}

__global__ void k_sigma(const float* __restrict__ ow, const float* __restrict__ ob){
    int row = blockIdx.x;                 // B*NT
    int b = row/NT, n = row%NT;
    int t = threadIdx.x;                  // 128
    __shared__ float red[128];
    red[t] = g_h2[((size_t)b*NP + n + 1)*HID + t] * ow[t];
    __syncthreads();
    for (int k=64;k>0;k>>=1){ if (t<k) red[t]+=red[t+k]; __syncthreads(); }
    if (t == 0) g_sig[row] = red[0] + ob[0];
}

// e = emb/(sigma+eps) and sq[row] = ||e_row||^2
__global__ void k_e(){
    int row = blockIdx.x;                 // B*NT
    int t = threadIdx.x;                  // 256
    float inv = 1.f/(g_sig[row] + 1e-6f);
    const float* src = g_emb + (size_t)row*DF;
    float* dst = g_e + (size_t)row*DF;
    float s = 0.f;
    for (int f=t;f<DF;f+=256){
        float v = src[f]*inv;
        dst[f] = v;
        s += v*v;
    }
    for (int off=16;off;off>>=1) s += __shfl_down_sync(0xFFFFFFFFu, s, off);
    __shared__ float ws[8];
    if ((t&31)==0) ws[t>>5] = s;
    __syncthreads();
    if (t == 0){
        float tot = ws[0];
        #pragma unroll
        for (int w=1;w<8;w++) tot += ws[w];
        g_sq[row] = tot;
    }
}

__global__ void k_topk(){
    int row = blockIdx.x;                 // B*NT
    const float* wr = g_Wm + (size_t)row*NT;
    unsigned char* mr = g_mask + (size_t)row*NT;
    __shared__ float vals[NT];
    __shared__ float wmax[8];
    __shared__ int   wimax[8];
    int t = threadIdx.x, lane = t&31, warp = t>>5;
    vals[t]=wr[t]; vals[t+256]=wr[t+256]; mr[t]=0; mr[t+256]=0;
    __syncthreads();
    for (int it=0; it<TOPKK; it++){
        float v1 = vals[t], v2 = vals[t+256];
        float bv; int bi;
        if (v1 >= v2){ bv=v1; bi=t; } else { bv=v2; bi=t+256; }
        #pragma unroll
        for (int off=16;off;off>>=1){
            float ov = __shfl_down_sync(0xFFFFFFFFu, bv, off);
            int   oi = __shfl_down_sync(0xFFFFFFFFu, bi, off);
            if (ov > bv || (ov==bv && oi<bi)){ bv=ov; bi=oi; }
        }
        if (lane==0){ wmax[warp]=bv; wimax[warp]=bi; }
        __syncthreads();
        if (t == 0){
            bv = wmax[0]; bi = wimax[0];
            #pragma unroll
            for (int w=1;w<8;w++)
                if (wmax[w] > bv || (wmax[w]==bv && wimax[w]<bi)){ bv=wmax[w]; bi=wimax[w]; }
            mr[bi] = 1; vals[bi] = -2e30f;
        }
        __syncthreads();
    }
}

// mask2 = mask | mask^T via coalesced 64x64 smem tile transpose
__global__ void k_masksym(){
    __shared__ unsigned char T[64][68];
    int b = blockIdx.z;
    int i0 = blockIdx.y*64, j0 = blockIdx.x*64;
    const unsigned char* M = g_mask + (size_t)b*NSQ;
    unsigned char* O = g_mask2 + (size_t)b*NSQ;
    int t = threadIdx.x;
    #pragma unroll
    for (int u=0;u<4;u++){
        int idx = t + u*256;
        int r = idx>>4, c4 = (idx&15)*4;
        unsigned int v = *(const unsigned int*)&M[(size_t)(j0+r)*NT + i0 + c4];
        *(unsigned int*)&T[r][c4] = v;
    }
    __syncthreads();
    #pragma unroll
    for (int u=0;u<4;u++){
        int idx = t + u*256;
        int r = idx>>4, c4 = (idx&15)*4;
        unsigned int a = *(const unsigned int*)&M[(size_t)(i0+r)*NT + j0 + c4];
        unsigned int tr = (unsigned int)T[c4+0][r]
                        | ((unsigned int)T[c4+1][r]<<8)
                        | ((unsigned int)T[c4+2][r]<<16)
                        | ((unsigned int)T[c4+3][r]<<24);
        *(unsigned int*)&O[(size_t)(i0+r)*NT + j0 + c4] = a | tr;
    }
}

__global__ void k_wmdeg(){
    int row = blockIdx.x;                 // B*NT
    float* wr = g_Wm + (size_t)row*NT;
    const unsigned char* mr = g_mask2 + (size_t)row*NT;
    __shared__ float red[256];
    int t = threadIdx.x;
    float s = 0.f;
    for (int j=t;j<NT;j+=256){
        float w = mr[j] ? wr[j] : 0.f;
        wr[j] = w; s += w;
    }
    red[t]=s; __syncthreads();
    for (int k=128;k>0;k>>=1){ if (t<k) red[t]+=red[t+k]; __syncthreads(); }
    if (t == 0) g_dsi[row] = sqrtf(1.0f/(red[0] + 1e-6f));
}

__global__ void k_buildA(const float* __restrict__ alpha){
    int idx = blockIdx.x*blockDim.x + threadIdx.x;
    if (idx >= BB*NSQ) return;
    int b = idx/NSQ, rem = idx - b*NSQ;
    int i = rem/NT, j = rem%NT;
    float v = -alpha[0] * g_dsi[b*NT+i] * g_Wm[idx] * g_dsi[b*NT+j];
    if (i == j) v += 1.0f + 1e-6f;
    g_A[idx] = v;
}

// merged: blocks [0,BB) invert pivot block; blocks [BB,..) copy row/col panels
__global__ void k_step1(int s){
    if (blockIdx.x < BB){
        int b = blockIdx.x;
        __shared__ float P[64][65];
        __shared__ float rb[64], cb[64];
        __shared__ float pvs;
        int t = threadIdx.x;
        float* Ab = g_A + (size_t)b*NSQ;
        for (int e=t;e<4096;e+=256)
            P[e>>6][e&63] = Ab[(size_t)(s*64 + (e>>6))*NT + s*64 + (e&63)];
        __syncthreads();
        for (int k=0;k<64;k++){
            if (t < 64){ rb[t] = P[k][t]; cb[t] = P[t][k]; }
            __syncthreads();
            if (t == 0) pvs = 1.0f/rb[k];
            __syncthreads();
            float pv = pvs;
            for (int e=t;e<4096;e+=256){
                int i = e>>6, j = e&63;
                float nv;
                if (i == k)      nv = (j == k) ? pv : rb[j]*pv;
                else if (j == k) nv = -cb[i]*pv;
                else             nv = P[i][j] - cb[i]*rb[j]*pv;
                P[i][j] = nv;
            }
            __syncthreads();
        }
        for (int e=t;e<4096;e+=256)
            g_Pinv[(size_t)b*4096 + e] = P[e>>6][e&63];
    } else {
        int idx = (blockIdx.x - BB)*256 + threadIdx.x;
        const int per = 2*64*NT;
        if (idx >= BB*per) return;
        int b = idx/per, r2 = idx - b*per;
        if (r2 < 64*NT){
            int r = r2/NT, j = r2%NT;
            g_Rpan[(size_t)b*64*NT + r2] = g_A[(size_t)b*NSQ + (size_t)(s*64+r)*NT + j];
        } else {
            int r3 = r2 - 64*NT;
            g_Cpan[(size_t)b*NT*64 + r3] = g_A[(size_t)b*NSQ + (size_t)(r3>>6)*NT + s*64 + (r3&63)];
        }
    }
}

__global__ void k_updpan(int s){
    int b = blockIdx.z;
    int job = blockIdx.x;                 // 0..7 row tiles, 8..15 col tiles
    __shared__ float Pv[64][65];
    __shared__ float T[64][65];
    int t = threadIdx.x, tx = t&15, ty = t>>4;
    float* Ab = g_A + (size_t)b*NSQ;
    for (int e=t;e<4096;e+=256) Pv[e>>6][e&63] = g_Pinv[(size_t)b*4096 + e];
    if (job < 8){
        int jb = job;
        if (jb == s){
            __syncthreads();
            for (int e=t;e<4096;e+=256)
                Ab[(size_t)(s*64 + (e>>6))*NT + s*64 + (e&63)] = Pv[e>>6][e&63];
            return;
        }
        for (int e=t;e<4096;e+=256)
            T[e>>6][e&63] = g_Rpan[(size_t)b*64*NT + (size_t)(e>>6)*NT + jb*64 + (e&63)];
        __syncthreads();
        float acc[4][4];
        #pragma unroll
        for (int i=0;i<4;i++){ acc[i][0]=0;acc[i][1]=0;acc[i][2]=0;acc[i][3]=0; }
        for (int kk=0;kk<64;kk++){
            float a[4], bb[4];
            #pragma unroll
            for (int i=0;i<4;i++){ a[i]=Pv[ty+16*i][kk]; bb[i]=T[kk][tx+16*i]; }
            #pragma unroll
            for (int i=0;i<4;i++)
                #pragma unroll
                for (int j=0;j<4;j++) acc[i][j] += a[i]*bb[j];
        }
        #pragma unroll
        for (int i=0;i<4;i++)
            #pragma unroll
            for (int j=0;j<4;j++)
                Ab[(size_t)(s*64 + ty+16*i)*NT + jb*64 + tx+16*j] = acc[i][j];
    } else {
        int ib = job - 8;
        if (ib == s) return;
        for (int e=t;e<4096;e+=256)
            T[e>>6][e&63] = g_Cpan[((size_t)b*NT + ib*64 + (e>>6))*64 + (e&63)];
        __syncthreads();
        float acc[4][4];
        #pragma unroll
        for (int i=0;i<4;i++){ acc[i][0]=0;acc[i][1]=0;acc[i][2]=0;acc[i][3]=0; }
        for (int kk=0;kk<64;kk++){
            float a[4], bb[4];
            #pragma unroll
            for (int i=0;i<4;i++){ a[i]=T[ty+16*i][kk]; bb[i]=Pv[kk][tx+16*i]; }
            #pragma unroll
            for (int i=0;i<4;i++)
                #pragma unroll
                for (int j=0;j<4;j++) acc[i][j] += a[i]*bb[j];
        }
        #pragma unroll
        for (int i=0;i<4;i++)
            #pragma unroll
            for (int j=0;j<4;j++)
                Ab[(size_t)(ib*64 + ty+16*i)*NT + s*64 + tx+16*j] = -acc[i][j];
    }
}

__global__ void k_interior(int s){
    int b = blockIdx.z, bi = blockIdx.y, bj = blockIdx.x;
    if (bi == s || bj == s) return;
    __shared__ float Ct[64][65];
    __shared__ float Rt[64][65];
    int t = threadIdx.x, tx = t&15, ty = t>>4;
    float* Ab = g_A + (size_t)b*NSQ;
    for (int e=t;e<4096;e+=256){
        int r = e>>6, c = e&63;
        Ct[r][c] = g_Cpan[((size_t)b*NT + bi*64 + r)*64 + c];
        Rt[r][c] = Ab[(size_t)(s*64 + r)*NT + bj*64 + c];   // NEW row panel
    }
    __syncthreads();
    float acc[4][4];
    #pragma unroll
    for (int i=0;i<4;i++){ acc[i][0]=0;acc[i][1]=0;acc[i][2]=0;acc[i][3]=0; }
    for (int kk=0;kk<64;kk++){
        float a[4], bb[4];
        #pragma unroll
        for (int i=0;i<4;i++){ a[i]=Ct[ty+16*i][kk]; bb[i]=Rt[kk][tx+16*i]; }
        #pragma unroll
        for (int i=0;i<4;i++)
            #pragma unroll
            for (int j=0;j<4;j++) acc[i][j] += a[i]*bb[j];
    }
    #pragma unroll
    for (int i=0;i<4;i++)
        #pragma unroll
        for (int j=0;j<4;j++)
            Ab[(size_t)(bi*64 + ty+16*i)*NT + bj*64 + tx+16*j] -= acc[i][j];
}

// per-row vocab accumulation in smem (64KB dynamic), then streamed out. No global memset.
__global__ void k_scatter(const int* __restrict__ labels, float* __restrict__ out){
    extern __shared__ float acc[];        // VOC floats
    int row = blockIdx.x;                 // B*NT
    int b = row/NT;
    int t = threadIdx.x;
    float4 z4 = {0.f,0.f,0.f,0.f};
    #pragma unroll
    for (int u=0;u<16;u++) *(float4*)&acc[(t + u*256)*4] = z4;
    __syncthreads();
    const float* pr = g_A + (size_t)row*NT;
    for (int m=t; m<NT; m+=256){
        int v = labels[b*NT + m];
        if ((unsigned)v < (unsigned)VOC) atomicAdd(&acc[v], pr[m]);
    }
    __syncthreads();
    float* orow = out + (size_t)row*VOC;
    #pragma unroll
    for (int u=0;u<16;u++){
        int i4 = (t + u*256)*4;
        *(float4*)&orow[i4] = *(float4*)&acc[i4];
    }
}

extern "C" void kernel_launch(void* const* d_in, const int* in_sizes, int n_in,
                              void* d_out, int out_size)
{
    const float* ge        = (const float*)d_in[0];
    const float* ue        = (const float*)d_in[1];
    const float* hs        = (const float*)d_in[2];
    const int*   labels    = (const int*)  d_in[3];
    const float* mha_in_w  = (const float*)d_in[4];
    const float* mha_in_b  = (const float*)d_in[5];
    const float* mha_out_w = (const float*)d_in[6];
    const float* mha_out_b = (const float*)d_in[7];
    const float* ln_g      = (const float*)d_in[8];
    const float* ln_b      = (const float*)d_in[9];
    const float* proj_w    = (const float*)d_in[10];
    const float* proj_b    = (const float*)d_in[11];
    const float* c1w       = (const float*)d_in[12];
    const float* c1b       = (const float*)d_in[13];
    const float* bn1g      = (const float*)d_in[14];
    const float* bn1b      = (const float*)d_in[15];
    const float* c2w       = (const float*)d_in[16];
    const float* c2b       = (const float*)d_in[17];
    const float* bn2g      = (const float*)d_in[18];
    const float* bn2b      = (const float*)d_in[19];
    const float* ow        = (const float*)d_in[20];
    const float* ob        = (const float*)d_in[21];
    const float* alpha     = (const float*)d_in[22];
    float* out = (float*)d_out;

    float *emb,*Q,*K,*V,*S,*AO,*xp,*h1,*h2,*e,*Wm,*sq,*w1r,*w2r;
    cudaGetSymbolAddress((void**)&emb, g_emb);
    cudaGetSymbolAddress((void**)&Q,   g_Q);
    cudaGetSymbolAddress((void**)&K,   g_K);
    cudaGetSymbolAddress((void**)&V,   g_V);
    cudaGetSymbolAddress((void**)&S,   g_S);
    cudaGetSymbolAddress((void**)&AO,  g_AO);
    cudaGetSymbolAddress((void**)&xp,  g_xp);
    cudaGetSymbolAddress((void**)&h1,  g_h1);
    cudaGetSymbolAddress((void**)&h2,  g_h2);
    cudaGetSymbolAddress((void**)&e,   g_e);
    cudaGetSymbolAddress((void**)&Wm,  g_Wm);
    cudaGetSymbolAddress((void**)&sq,  g_sq);
    cudaGetSymbolAddress((void**)&w1r, g_w1r);
    cudaGetSymbolAddress((void**)&w2r, g_w2r);

    cudaFuncSetAttribute(k_scatter, cudaFuncAttributeMaxDynamicSharedMemorySize, VOC*4);

    dim3 thr(256);

    k_emb<<<(BB*NT*DF+255)/256,256>>>(ge, ue);

    // QKV projections
    k_gemm2<<<dim3(12,2,BB), thr>>>(emb + (size_t)IQ*DF, DF, (long long)NT*DF, 0,
        mha_in_w, DF, 0, 0, Q, DF, (long long)IQ*DF, 0, DF, 1, mha_in_b, 1.f, 0, 1, nullptr);
    k_gemm2<<<dim3(12,4,BB), thr>>>(hs, DF, (long long)NT*DF, 0,
        mha_in_w + DF*DF, DF, 0, 0, K, DF, (long long)NT*DF, 0, DF, 1, mha_in_b+DF, 1.f, 0, 1, nullptr);
    k_gemm2<<<dim3(12,4,BB), thr>>>(hs, DF, (long long)NT*DF, 0,
        mha_in_w + 2*DF*DF, DF, 0, 0, V, DF, (long long)NT*DF, 0, DF, 1, mha_in_b+2*DF, 1.f, 0, 1, nullptr);

    // attention
    k_gemm2<<<dim3(8,2,BB*NHEAD), thr>>>(Q, DF, (long long)IQ*DF, HD,
        K, DF, (long long)NT*DF, HD, S, NT, (long long)NHEAD*IQ*NT, (long long)IQ*NT,
        HD, NHEAD, nullptr, 0.125f, 0, 1, nullptr);
    k_softmax<<<BB*NHEAD*IQ, 256>>>();
    k_gemm2<<<dim3(1,2,BB*NHEAD), thr>>>(S, NT, (long long)NHEAD*IQ*NT, (long long)IQ*NT,
        V, DF, (long long)NT*DF, HD, AO, DF, (long long)IQ*DF, HD,
        NT, NHEAD, nullptr, 1.f, 0, 0, nullptr);

    // out proj -> g_Q, residual + LN
    k_gemm2<<<dim3(12,2,BB), thr>>>(AO, DF, (long long)IQ*DF, 0,
        mha_out_w, DF, 0, 0, Q, DF, (long long)IQ*DF, 0, DF, 1, mha_out_b, 1.f, 0, 1, nullptr);
    k_addln<<<BB*IQ, 256>>>(ln_g, ln_b);

    // proj + conv stack
    k_repack<<<(3*HID*PROJ + 3*HID*HID + 255)/256,256>>>(c1w, c2w);
    k_zeropad<<<(BB*PROJ+255)/256,256>>>();
    k_gemm2<<<dim3(4,4,BB), thr>>>(emb, DF, (long long)NT*DF, 0,
        proj_w, DF, 0, 0, xp + PROJ, PROJ, (long long)NP*PROJ, 0,
        DF, 1, proj_b, 1.f, 0, 1, nullptr);
    for (int dt=0; dt<3; dt++)
        k_gemm2<<<dim3(2,4,BB), thr>>>(xp + dt*PROJ, PROJ, (long long)NP*PROJ, 0,
            w1r + dt*HID*PROJ, PROJ, 0, 0, h1 + HID, HID, (long long)NP*HID, 0,
            PROJ, 1, dt==0?c1b:nullptr, 1.f, dt>0, 1, nullptr);
    k_bnrelu<<<(BB*NT*HID+255)/256,256>>>(h1, bn1g, bn1b, HID);
    for (int dt=0; dt<3; dt++)
        k_gemm2<<<dim3(2,4,BB), thr>>>(h1 + dt*HID, HID, (long long)NP*HID, 0,
            w2r + dt*HID*HID, HID, 0, 0, h2 + HID, HID, (long long)NP*HID, 0,
            HID, 1, dt==0?c2b:nullptr, 1.f, dt>0, 1, nullptr);
    k_bnrelu<<<(BB*NT*HID+255)/256,256>>>(h2, bn2g, bn2b, HID);
    k_sigma<<<BB*NT, HID>>>(ow, ob);

    // e + row norms, fused gram->W, topk mask, sym-mask, degrees, A
    k_e<<<BB*NT, 256>>>();
    k_gemm2<<<dim3(8,4,BB), thr>>>(e, DF, (long long)NT*DF, 0,
        e, DF, (long long)NT*DF, 0, Wm, NT, (long long)NSQ, 0,
        DF, 1, nullptr, 1.f, 0, 1, sq);
    k_topk<<<BB*NT, 256>>>();
    k_masksym<<<dim3(8,8,BB), 256>>>();
    k_wmdeg<<<BB*NT, 256>>>();
    k_buildA<<<(BB*NSQ+255)/256,256>>>(alpha);

    // blocked Gauss-Jordan inversion (SPD, no pivoting), nb=64
    for (int s=0; s<8; s++){
        k_step1<<<BB + (BB*2*64*NT+255)/256, 256>>>(s);
        k_updpan<<<dim3(16,1,BB), 256>>>(s);
        k_interior<<<dim3(8,8,BB), 256>>>(s);
    }

    // out = prop @ one_hot(labels): smem-resident per-row scatter
    k_scatter<<<BB*NT, 256, VOC*4>>>(labels, out);
}